// round 10
// baseline (speedup 1.0000x reference)
#include <cuda_runtime.h>
#include <math.h>

// ---------------- problem constants ----------------
constexpr int BSZ  = 32;
constexpr int NN   = 243;
constexpr int DD   = 544;
constexpr int HH   = 8;
constexpr int HD   = 68;          // DD/HH
constexpr int NS   = 17;
constexpr int UD   = 1088;        // UP*DD
constexpr int UC   = 136;         // UD/HH
constexpr int MLP1 = 2176;        // 4*DD
constexpr int MLP2 = 1088;        // 2*DD
constexpr int BT   = BSZ * NN;    // 7776 tokens
constexpr int TD   = 3 * DD;      // 1632
constexpr long long X_ELEMS = (long long)BT * DD;  // 4,230,144

// ---------------- scratch (device globals; no allocation) ----------------
__device__ float g_h   [BT * DD];
__device__ float g_qkv [BT * TD];
__device__ float g_o   [BT * DD];
__device__ float g_x1  [BT * DD];
__device__ float g_x2  [BT * DD];
__device__ float g_x3  [BT * DD];
__device__ float g_mlp [BT * MLP1];
__device__ float g_xu  [BT * UD];
__device__ float g_o2  [BT * UD];
__device__ float g_s0  [NS * UD];
__device__ float g_s1  [NS * UD];
__device__ float g_a   [BSZ * HH * NS * NN];  // layout [b][h][n][f]

// ---------------- reduction helpers ----------------
__device__ __forceinline__ float block_sum(float v, float* red) {
    int lane = threadIdx.x & 31, wid = threadIdx.x >> 5;
    #pragma unroll
    for (int o = 16; o > 0; o >>= 1) v += __shfl_xor_sync(0xffffffffu, v, o);
    if (lane == 0) red[wid] = v;
    __syncthreads();
    int nw = (blockDim.x + 31) >> 5;
    float r = (threadIdx.x < nw) ? red[threadIdx.x] : 0.f;
    #pragma unroll
    for (int o = 16; o > 0; o >>= 1) r += __shfl_xor_sync(0xffffffffu, r, o);
    if (threadIdx.x == 0) red[0] = r;
    __syncthreads();
    r = red[0];
    __syncthreads();
    return r;
}

__device__ __forceinline__ float block_max(float v, float* red) {
    int lane = threadIdx.x & 31, wid = threadIdx.x >> 5;
    #pragma unroll
    for (int o = 16; o > 0; o >>= 1) v = fmaxf(v, __shfl_xor_sync(0xffffffffu, v, o));
    if (lane == 0) red[wid] = v;
    __syncthreads();
    int nw = (blockDim.x + 31) >> 5;
    float r = (threadIdx.x < nw) ? red[threadIdx.x] : -3.4e38f;
    #pragma unroll
    for (int o = 16; o > 0; o >>= 1) r = fmaxf(r, __shfl_xor_sync(0xffffffffu, r, o));
    if (threadIdx.x == 0) red[0] = r;
    __syncthreads();
    r = red[0];
    __syncthreads();
    return r;
}

__device__ __forceinline__ float gelu_exact(float v) {
    return 0.5f * v * (1.0f + erff(v * 0.70710678118654752f));
}

// ---------------- LayerNorm: one block per row ----------------
__global__ void ln_kernel(const float* __restrict__ x, const float* __restrict__ g,
                          const float* __restrict__ b, float* __restrict__ out) {
    __shared__ float red[8];
    int row = blockIdx.x;
    const float* xr = x + (size_t)row * DD;
    float s = 0.f, s2 = 0.f;
    for (int i = threadIdx.x; i < DD; i += blockDim.x) {
        float v = xr[i]; s += v; s2 += v * v;
    }
    s  = block_sum(s,  red);
    s2 = block_sum(s2, red);
    float m    = s  * (1.0f / DD);
    float var  = s2 * (1.0f / DD) - m * m;
    float rstd = rsqrtf(var + 1e-5f);
    float* orow = out + (size_t)row * DD;
    for (int i = threadIdx.x; i < DD; i += blockDim.x)
        orow[i] = (xr[i] - m) * rstd * g[i] + b[i];
}

// ---------------- Tiled SGEMM: C[M,Nc] = A[M,K] @ W[Nc,K]^T (+epilogue) ----------
// 128x128x16 tiles, 256 threads, 8x8 microtile.
// EPI: 0 = none, 1 = +bias, 2 = gelu(+bias), 3 = res + (+bias)
template <int EPI>
__global__ __launch_bounds__(256)
void gemm_kernel(const float* __restrict__ A, const float* __restrict__ W,
                 const float* __restrict__ bias, const float* __restrict__ res,
                 float* __restrict__ C, int M, int Nc, int K) {
    __shared__ float As[16][128];
    __shared__ float Bs[16][128];
    int tid = threadIdx.x;
    int rowBase = blockIdx.y * 128;
    int colBase = blockIdx.x * 128;
    int tx = tid & 15, ty = tid >> 4;

    // loader coords: each thread loads 2 float4 from A and 2 from B per k-tile
    int ldr = tid >> 2;          // 0..63
    int ldc = (tid & 3) * 4;     // 0,4,8,12

    float acc[8][8];
    #pragma unroll
    for (int i = 0; i < 8; i++)
        #pragma unroll
        for (int j = 0; j < 8; j++) acc[i][j] = 0.f;

    for (int k0 = 0; k0 < K; k0 += 16) {
        #pragma unroll
        for (int it = 0; it < 2; it++) {
            int rl = ldr + it * 64;
            int r  = rowBase + rl;
            float4 v = make_float4(0.f, 0.f, 0.f, 0.f);
            if (r < M) v = *reinterpret_cast<const float4*>(A + (size_t)r * K + k0 + ldc);
            As[ldc + 0][rl] = v.x; As[ldc + 1][rl] = v.y;
            As[ldc + 2][rl] = v.z; As[ldc + 3][rl] = v.w;

            int cl = ldr + it * 64;
            int c  = colBase + cl;
            float4 w4 = make_float4(0.f, 0.f, 0.f, 0.f);
            if (c < Nc) w4 = *reinterpret_cast<const float4*>(W + (size_t)c * K + k0 + ldc);
            Bs[ldc + 0][cl] = w4.x; Bs[ldc + 1][cl] = w4.y;
            Bs[ldc + 2][cl] = w4.z; Bs[ldc + 3][cl] = w4.w;
        }
        __syncthreads();
        #pragma unroll
        for (int kk = 0; kk < 16; kk++) {
            float av[8], bv[8];
            float4 a0 = *reinterpret_cast<float4*>(&As[kk][ty * 8]);
            float4 a1 = *reinterpret_cast<float4*>(&As[kk][ty * 8 + 4]);
            float4 b0 = *reinterpret_cast<float4*>(&Bs[kk][tx * 8]);
            float4 b1 = *reinterpret_cast<float4*>(&Bs[kk][tx * 8 + 4]);
            av[0]=a0.x; av[1]=a0.y; av[2]=a0.z; av[3]=a0.w;
            av[4]=a1.x; av[5]=a1.y; av[6]=a1.z; av[7]=a1.w;
            bv[0]=b0.x; bv[1]=b0.y; bv[2]=b0.z; bv[3]=b0.w;
            bv[4]=b1.x; bv[5]=b1.y; bv[6]=b1.z; bv[7]=b1.w;
            #pragma unroll
            for (int i = 0; i < 8; i++)
                #pragma unroll
                for (int j = 0; j < 8; j++) acc[i][j] += av[i] * bv[j];
        }
        __syncthreads();
    }

    #pragma unroll
    for (int i = 0; i < 8; i++) {
        int r = rowBase + ty * 8 + i;
        if (r >= M) continue;
        #pragma unroll
        for (int j = 0; j < 8; j++) {
            int c = colBase + tx * 8 + j;
            if (c >= Nc) continue;
            float v = acc[i][j];
            if (EPI >= 1) v += bias[c];
            if (EPI == 2) v = gelu_exact(v);
            if (EPI == 3) v += res[(size_t)r * Nc + c];
            C[(size_t)r * Nc + c] = v;
        }
    }
}

// ---------------- Attention: one block per (b,h,i) ----------------
__global__ void attn_kernel(const float* __restrict__ qkv,
                            const float* __restrict__ b_table,
                            float* __restrict__ o) {
    __shared__ float qs[HD];
    __shared__ float sc[NN];
    __shared__ float red[4];
    int blk = blockIdx.x;
    int i  = blk % NN;
    int bh = blk / NN;
    int h  = bh % HH;
    int b  = bh / HH;
    const float scale = 0.12126781251816648f;  // 1/sqrt(68)

    const float* qp = qkv + (size_t)(b * NN + i) * TD + h * HD;
    for (int t = threadIdx.x; t < HD; t += blockDim.x) qs[t] = qp[t];
    __syncthreads();

    const float* bt    = b_table + h * (2 * NN - 1) + (i + NN - 1);
    const float* kbase = qkv + (size_t)b * NN * TD + DD + h * HD;
    float lmax = -3.4e38f;
    for (int j = threadIdx.x; j < NN; j += blockDim.x) {
        const float* kp = kbase + (size_t)j * TD;
        float s = 0.f;
        #pragma unroll 4
        for (int d = 0; d < HD; d++) s += qs[d] * kp[d];
        s = s * scale + bt[-j];
        sc[j] = s;
        lmax = fmaxf(lmax, s);
    }
    float m = block_max(lmax, red);
    float lsum = 0.f;
    for (int j = threadIdx.x; j < NN; j += blockDim.x) {
        float e = expf(sc[j] - m);
        sc[j] = e;
        lsum += e;
    }
    float ssum = block_sum(lsum, red);
    float inv = 1.f / ssum;

    const float* vbase = qkv + (size_t)b * NN * TD + 2 * DD + h * HD;
    for (int d = threadIdx.x; d < HD; d += blockDim.x) {
        float accv = 0.f;
        for (int j = 0; j < NN; j++) accv += sc[j] * vbase[(size_t)j * TD + d];
        o[(size_t)(b * NN + i) * DD + h * HD + d] = accv * inv;
    }
}

// ---------------- Seed attention scores: a[b,h,n,f] ----------------
__global__ void seed_scores_kernel(const float* __restrict__ xu,
                                   const float* __restrict__ s0,
                                   float* __restrict__ a) {
    __shared__ float xs[UD];
    int t = blockIdx.x;              // token = b*NN + f
    int b = t / NN, f = t % NN;
    for (int i = threadIdx.x; i < UD; i += blockDim.x)
        xs[i] = xu[(size_t)t * UD + i];
    __syncthreads();
    int oi = threadIdx.x;
    if (oi < HH * NS) {
        int h = oi / NS, n = oi % NS;
        const float* sp = s0 + n * UD + h * UC;
        const float* xp = xs + h * UC;
        float accv = 0.f;
        #pragma unroll 8
        for (int c = 0; c < UC; c++) accv += xp[c] * sp[c];
        a[((size_t)(b * HH + h) * NS + n) * NN + f] = accv;
    }
}

// ---------------- softmax over f (contiguous rows of length NN) ----------
__global__ void softmax_f_kernel(float* __restrict__ a) {
    __shared__ float red[4];
    int row = blockIdx.x;            // b*H*NS rows
    float* p = a + (size_t)row * NN;
    float lmax = -3.4e38f;
    for (int f = threadIdx.x; f < NN; f += blockDim.x) lmax = fmaxf(lmax, p[f]);
    float m = block_max(lmax, red);
    float lsum = 0.f;
    for (int f = threadIdx.x; f < NN; f += blockDim.x) {
        float e = expf(p[f] - m);
        p[f] = e;
        lsum += e;
    }
    float s = block_sum(lsum, red);
    float inv = 1.f / s;
    for (int f = threadIdx.x; f < NN; f += blockDim.x) p[f] *= inv;
}

// ---------------- normalize over n: a /= (1e-7 + sum_n a) --------------
__global__ void seed_norm_kernel(float* __restrict__ a) {
    int idx = blockIdx.x * blockDim.x + threadIdx.x;  // over (bh, f)
    if (idx >= BSZ * HH * NN) return;
    int f  = idx % NN;
    int bh = idx / NN;
    float* base = a + (size_t)bh * NS * NN + f;
    float s = 0.f;
    #pragma unroll
    for (int n = 0; n < NS; n++) s += base[n * NN];
    float inv = 1.f / (1e-7f + s);
    #pragma unroll
    for (int n = 0; n < NS; n++) base[n * NN] *= inv;
}

// ---------------- mean_attn: one block per seed n ----------------------
__global__ void mean_kernel(const float* __restrict__ a, float* __restrict__ out_mean) {
    __shared__ float red[8];
    int n = blockIdx.x;  // 0..16
    float s = 0.f;
    int total = BSZ * HH * NN;
    for (int i = threadIdx.x; i < total; i += blockDim.x) {
        int f  = i % NN;
        int bh = i / NN;
        s += a[((size_t)bh * NS + n) * NN + f];
    }
    s = block_sum(s, red);
    if (threadIdx.x == 0) out_mean[n] = s * (1.0f / (BSZ * HH * NN));
}

// ---------------- o2[t, h*UC+c] = sum_n a[b,h,n,f] * s1[h,n,c] ----------
__global__ void seed_out_kernel(const float* __restrict__ a,
                                const float* __restrict__ s1,
                                float* __restrict__ o2) {
    int idx = blockIdx.x * blockDim.x + threadIdx.x;
    if (idx >= BT * UD) return;
    int c    = idx % UC;
    int rest = idx / UC;
    int h    = rest % HH;
    int t    = rest / HH;     // b*NN + f
    int b = t / NN, f = t % NN;
    const float* ap = a + (size_t)(b * HH + h) * NS * NN + f;
    const float* sp = s1 + h * UC + c;
    float accv = 0.f;
    #pragma unroll
    for (int n = 0; n < NS; n++) accv += ap[n * NN] * sp[(size_t)n * UD];
    o2[idx] = accv;
}

// ---------------- driver ----------------
static inline dim3 gemm_grid(int M, int Nc) {
    return dim3((Nc + 127) / 128, (M + 127) / 128);
}

extern "C" void kernel_launch(void* const* d_in, const int* in_sizes, int n_in,
                              void* d_out, int out_size) {
    const float* x       = (const float*)d_in[0];
    const float* seed    = (const float*)d_in[1];
    const float* ln1_g   = (const float*)d_in[2];
    const float* ln1_b   = (const float*)d_in[3];
    const float* w_qkv   = (const float*)d_in[4];
    const float* w_proj  = (const float*)d_in[5];
    const float* b_proj  = (const float*)d_in[6];
    const float* b_table = (const float*)d_in[7];
    const float* ln2_g   = (const float*)d_in[8];
    const float* ln2_b   = (const float*)d_in[9];
    const float* mlp_w1  = (const float*)d_in[10];
    const float* mlp_b1  = (const float*)d_in[11];
    const float* mlp_w2  = (const float*)d_in[12];
    const float* mlp_b2  = (const float*)d_in[13];
    const float* eln1_g  = (const float*)d_in[14];
    const float* eln1_b  = (const float*)d_in[15];
    const float* w_trans = (const float*)d_in[16];
    const float* b_trans = (const float*)d_in[17];
    const float* w0      = (const float*)d_in[18];
    const float* b0      = (const float*)d_in[19];
    const float* w1      = (const float*)d_in[20];
    const float* b1      = (const float*)d_in[21];
    const float* w_proj2 = (const float*)d_in[22];
    const float* b_proj2 = (const float*)d_in[23];
    const float* eln2_g  = (const float*)d_in[24];
    const float* eln2_b  = (const float*)d_in[25];
    const float* emlp_w1 = (const float*)d_in[26];
    const float* emlp_b1 = (const float*)d_in[27];
    const float* emlp_w2 = (const float*)d_in[28];
    const float* emlp_b2 = (const float*)d_in[29];

    float* out = (float*)d_out;

    float *ph, *pqkv, *po, *px1, *px2, *px3, *pmlp, *pxu, *po2, *ps0, *ps1, *pa;
    cudaGetSymbolAddress((void**)&ph,   g_h);
    cudaGetSymbolAddress((void**)&pqkv, g_qkv);
    cudaGetSymbolAddress((void**)&po,   g_o);
    cudaGetSymbolAddress((void**)&px1,  g_x1);
    cudaGetSymbolAddress((void**)&px2,  g_x2);
    cudaGetSymbolAddress((void**)&px3,  g_x3);
    cudaGetSymbolAddress((void**)&pmlp, g_mlp);
    cudaGetSymbolAddress((void**)&pxu,  g_xu);
    cudaGetSymbolAddress((void**)&po2,  g_o2);
    cudaGetSymbolAddress((void**)&ps0,  g_s0);
    cudaGetSymbolAddress((void**)&ps1,  g_s1);
    cudaGetSymbolAddress((void**)&pa,   g_a);

    // ---- block 1: self-attention + MLP ----
    ln_kernel<<<BT, 256>>>(x, ln1_g, ln1_b, ph);
    gemm_kernel<0><<<gemm_grid(BT, TD), 256>>>(ph, w_qkv, nullptr, nullptr, pqkv, BT, TD, DD);
    attn_kernel<<<BSZ * HH * NN, 128>>>(pqkv, b_table, po);
    gemm_kernel<3><<<gemm_grid(BT, DD), 256>>>(po, w_proj, b_proj, x, px1, BT, DD, DD);
    ln_kernel<<<BT, 256>>>(px1, ln2_g, ln2_b, ph);
    gemm_kernel<2><<<gemm_grid(BT, MLP1), 256>>>(ph, mlp_w1, mlp_b1, nullptr, pmlp, BT, MLP1, DD);
    gemm_kernel<3><<<gemm_grid(BT, DD), 256>>>(pmlp, mlp_w2, mlp_b2, px1, px2, BT, DD, MLP1);

    // ---- block 2: seed attention ----
    ln_kernel<<<BT, 256>>>(px2, eln1_g, eln1_b, ph);
    gemm_kernel<1><<<gemm_grid(BT, UD), 256>>>(ph, w_trans, b_trans, nullptr, pxu, BT, UD, DD);
    gemm_kernel<1><<<gemm_grid(NS, UD), 256>>>(seed, w0, b0, nullptr, ps0, NS, UD, DD);
    gemm_kernel<1><<<gemm_grid(NS, UD), 256>>>(seed, w1, b1, nullptr, ps1, NS, UD, DD);
    seed_scores_kernel<<<BT, 160>>>(pxu, ps0, pa);
    softmax_f_kernel<<<BSZ * HH * NS, 128>>>(pa);
    seed_norm_kernel<<<(BSZ * HH * NN + 255) / 256, 256>>>(pa);
    mean_kernel<<<NS, 256>>>(pa, out + X_ELEMS);
    seed_out_kernel<<<(BT * UD + 255) / 256, 256>>>(pa, ps1, po2);
    gemm_kernel<3><<<gemm_grid(BT, DD), 256>>>(po2, w_proj2, b_proj2, px2, px3, BT, DD, UD);

    // ---- block 3: final MLP (writes x into d_out) ----
    ln_kernel<<<BT, 256>>>(px3, eln2_g, eln2_b, ph);
    gemm_kernel<2><<<gemm_grid(BT, MLP2), 256>>>(ph, emlp_w1, emlp_b1, nullptr, pmlp, BT, MLP2, DD);
    gemm_kernel<3><<<gemm_grid(BT, DD), 256>>>(pmlp, emlp_w2, emlp_b2, px3, out, BT, DD, MLP2);
}

// round 16
// speedup vs baseline: 3.5607x; 3.5607x over previous
#include <cuda_runtime.h>
#include <math.h>
#include <stdint.h>

// ---------------- problem constants ----------------
constexpr int BSZ  = 32;
constexpr int NN   = 243;
constexpr int DD   = 544;
constexpr int HH   = 8;
constexpr int HD   = 68;          // DD/HH
constexpr int NS   = 17;
constexpr int UD   = 1088;        // UP*DD
constexpr int UC   = 136;         // UD/HH
constexpr int MLP1 = 2176;        // 4*DD
constexpr int MLP2 = 1088;        // 2*DD
constexpr int BT   = BSZ * NN;    // 7776 tokens
constexpr int TD   = 3 * DD;      // 1632
constexpr long long X_ELEMS = (long long)BT * DD;  // 4,230,144

// ---------------- scratch (device globals; no allocation) ----------------
__device__ float g_h   [BT * DD];
__device__ float g_qkv [BT * TD];
__device__ float g_o   [BT * DD];
__device__ float g_x1  [BT * DD];
__device__ float g_x2  [BT * DD];
__device__ float g_x3  [BT * DD];
__device__ float g_mlp [BT * MLP1];
__device__ float g_xu  [BT * UD];
__device__ float g_o2  [BT * UD];
__device__ float g_s0  [NS * UD];
__device__ float g_s1  [NS * UD];
__device__ float g_a   [BSZ * HH * NS * NN];  // layout [b][h][n][f]

// ================= helpers =================
__device__ __forceinline__ uint32_t smem_u32(const void* p) {
    uint32_t a;
    asm("{ .reg .u64 t; cvta.to.shared.u64 t, %1; cvt.u32.u64 %0, t; }"
        : "=r"(a) : "l"(p));
    return a;
}
__device__ __forceinline__ uint32_t f2tf(float f) {
    uint32_t r;
    asm("cvt.rna.tf32.f32 %0, %1;" : "=r"(r) : "f"(f));
    return r;
}
__device__ __forceinline__ float gelu_exact(float v) {
    return 0.5f * v * (1.0f + erff(v * 0.70710678118654752f));
}

// ================= mma.sync tf32 GEMM =================
// C[M,Nc] = A[M,K] @ W[Nc,K]^T (+epilogue). K % 32 == 0.
// 128x128x32 CTA tile, 256 threads (8 warps, 2x4), warp tile 64x32.
// SMEM: A/B tiles stored [row][k] with stride 36 floats (conflict-free 4g+c).
// Double-buffered via cp.async.cg. EPI: 0 none, 1 +bias, 2 gelu(+bias), 3 res+(+bias)
constexpr int GEMM_BUF_F = 128 * 36;               // 4608 floats = 18432 B
constexpr int GEMM_SMEM  = 4 * GEMM_BUF_F * 4;     // 73728 B

template <int EPI>
__global__ __launch_bounds__(256, 2)
void mma_gemm(const float* __restrict__ A, const float* __restrict__ W,
              const float* __restrict__ bias, const float* __restrict__ res,
              float* __restrict__ C, int M, int Nc, int K) {
    extern __shared__ float sm[];
    const int tid  = threadIdx.x;
    const int wid  = tid >> 5;
    const int lane = tid & 31;
    const int wr = wid >> 2;       // 0..1  (64-row half)
    const int wc = wid & 3;        // 0..3  (32-col quarter)
    const int g  = lane >> 2;      // 0..7
    const int cq = lane & 3;       // 0..3
    const int rowBase = blockIdx.y * 128;
    const int colBase = blockIdx.x * 128;
    const uint32_t sb = smem_u32(sm);

    float c[4][4][4];
    #pragma unroll
    for (int i = 0; i < 4; i++)
        #pragma unroll
        for (int j = 0; j < 4; j++) {
            c[i][j][0] = 0.f; c[i][j][1] = 0.f; c[i][j][2] = 0.f; c[i][j][3] = 0.f;
        }

    const int ntile = K >> 5;

    // prefetch a k-tile into buffer `buf` (A at 0/1, B at 2/3)
    auto prefetch = [&](int kt, int buf) {
        const int k0 = kt << 5;
        #pragma unroll
        for (int it = 0; it < 4; it++) {
            int f   = it * 256 + tid;     // 0..1023
            int row = f >> 3;
            int c4  = f & 7;
            {   // A
                const float* src = A + (size_t)(rowBase + row) * K + k0 + c4 * 4;
                uint32_t dst = sb + (uint32_t)(buf * GEMM_BUF_F + row * 36 + c4 * 4) * 4u;
                int sz = (rowBase + row < M) ? 16 : 0;
                asm volatile("cp.async.cg.shared.global [%0], [%1], 16, %2;"
                             :: "r"(dst), "l"(src), "r"(sz));
            }
            {   // B (= W rows)
                const float* src = W + (size_t)(colBase + row) * K + k0 + c4 * 4;
                uint32_t dst = sb + (uint32_t)((2 + buf) * GEMM_BUF_F + row * 36 + c4 * 4) * 4u;
                int sz = (colBase + row < Nc) ? 16 : 0;
                asm volatile("cp.async.cg.shared.global [%0], [%1], 16, %2;"
                             :: "r"(dst), "l"(src), "r"(sz));
            }
        }
        asm volatile("cp.async.commit_group;" ::: "memory");
    };

    prefetch(0, 0);

    for (int kt = 0; kt < ntile; kt++) {
        const int buf = kt & 1;
        if (kt + 1 < ntile) {
            prefetch(kt + 1, buf ^ 1);
            asm volatile("cp.async.wait_group 1;" ::: "memory");
        } else {
            asm volatile("cp.async.wait_group 0;" ::: "memory");
        }
        __syncthreads();

        const float* As = sm + buf * GEMM_BUF_F;
        const float* Bs = sm + (2 + buf) * GEMM_BUF_F;

        #pragma unroll
        for (int ks = 0; ks < 4; ks++) {
            const int k0 = ks * 8;
            uint32_t bfr[4][2];
            #pragma unroll
            for (int nt = 0; nt < 4; nt++) {
                int col = wc * 32 + nt * 8 + g;
                bfr[nt][0] = f2tf(Bs[col * 36 + k0 + cq]);
                bfr[nt][1] = f2tf(Bs[col * 36 + k0 + cq + 4]);
            }
            #pragma unroll
            for (int mt = 0; mt < 4; mt++) {
                int row = wr * 64 + mt * 16 + g;
                uint32_t a0 = f2tf(As[row * 36 + k0 + cq]);
                uint32_t a1 = f2tf(As[(row + 8) * 36 + k0 + cq]);
                uint32_t a2 = f2tf(As[row * 36 + k0 + cq + 4]);
                uint32_t a3 = f2tf(As[(row + 8) * 36 + k0 + cq + 4]);
                #pragma unroll
                for (int nt = 0; nt < 4; nt++) {
                    asm volatile(
                        "mma.sync.aligned.m16n8k8.row.col.f32.tf32.tf32.f32 "
                        "{%0,%1,%2,%3}, {%4,%5,%6,%7}, {%8,%9}, {%0,%1,%2,%3};"
                        : "+f"(c[mt][nt][0]), "+f"(c[mt][nt][1]),
                          "+f"(c[mt][nt][2]), "+f"(c[mt][nt][3])
                        : "r"(a0), "r"(a1), "r"(a2), "r"(a3),
                          "r"(bfr[nt][0]), "r"(bfr[nt][1]));
                }
            }
        }
        __syncthreads();
    }

    // ---- epilogue ----
    #pragma unroll
    for (int mt = 0; mt < 4; mt++) {
        int rbase = rowBase + wr * 64 + mt * 16 + g;
        #pragma unroll
        for (int nt = 0; nt < 4; nt++) {
            int cc = colBase + wc * 32 + nt * 8 + 2 * cq;
            if (cc >= Nc) continue;
            float2 b2 = make_float2(0.f, 0.f);
            if (EPI >= 1) b2 = *reinterpret_cast<const float2*>(bias + cc);
            #pragma unroll
            for (int rr = 0; rr < 2; rr++) {
                int r = rbase + rr * 8;
                if (r >= M) continue;
                float v0 = c[mt][nt][rr * 2 + 0];
                float v1 = c[mt][nt][rr * 2 + 1];
                if (EPI >= 1) { v0 += b2.x; v1 += b2.y; }
                if (EPI == 2) { v0 = gelu_exact(v0); v1 = gelu_exact(v1); }
                if (EPI == 3) {
                    float2 r2 = *reinterpret_cast<const float2*>(res + (size_t)r * Nc + cc);
                    v0 += r2.x; v1 += r2.y;
                }
                *reinterpret_cast<float2*>(C + (size_t)r * Nc + cc) = make_float2(v0, v1);
            }
        }
    }
}

// ================= reduction helpers (block) =================
__device__ __forceinline__ float block_sum(float v, float* red) {
    int lane = threadIdx.x & 31, wid = threadIdx.x >> 5;
    #pragma unroll
    for (int o = 16; o > 0; o >>= 1) v += __shfl_xor_sync(0xffffffffu, v, o);
    if (lane == 0) red[wid] = v;
    __syncthreads();
    int nw = (blockDim.x + 31) >> 5;
    float r = (threadIdx.x < nw) ? red[threadIdx.x] : 0.f;
    #pragma unroll
    for (int o = 16; o > 0; o >>= 1) r += __shfl_xor_sync(0xffffffffu, r, o);
    if (threadIdx.x == 0) red[0] = r;
    __syncthreads();
    r = red[0];
    __syncthreads();
    return r;
}
__device__ __forceinline__ float block_max(float v, float* red) {
    int lane = threadIdx.x & 31, wid = threadIdx.x >> 5;
    #pragma unroll
    for (int o = 16; o > 0; o >>= 1) v = fmaxf(v, __shfl_xor_sync(0xffffffffu, v, o));
    if (lane == 0) red[wid] = v;
    __syncthreads();
    int nw = (blockDim.x + 31) >> 5;
    float r = (threadIdx.x < nw) ? red[threadIdx.x] : -3.4e38f;
    #pragma unroll
    for (int o = 16; o > 0; o >>= 1) r = fmaxf(r, __shfl_xor_sync(0xffffffffu, r, o));
    if (threadIdx.x == 0) red[0] = r;
    __syncthreads();
    r = red[0];
    __syncthreads();
    return r;
}

// ---------------- LayerNorm: one block per row ----------------
__global__ void ln_kernel(const float* __restrict__ x, const float* __restrict__ g,
                          const float* __restrict__ b, float* __restrict__ out) {
    __shared__ float red[8];
    int row = blockIdx.x;
    const float* xr = x + (size_t)row * DD;
    float s = 0.f, s2 = 0.f;
    for (int i = threadIdx.x; i < DD; i += blockDim.x) {
        float v = xr[i]; s += v; s2 += v * v;
    }
    s  = block_sum(s,  red);
    s2 = block_sum(s2, red);
    float m    = s  * (1.0f / DD);
    float var  = s2 * (1.0f / DD) - m * m;
    float rstd = rsqrtf(var + 1e-5f);
    float* orow = out + (size_t)row * DD;
    for (int i = threadIdx.x; i < DD; i += blockDim.x)
        orow[i] = (xr[i] - m) * rstd * g[i] + b[i];
}

// ---------------- scalar SGEMM (tiny seed GEMMs, M=17) -----
__global__ __launch_bounds__(256)
void gemm_scalar_bias(const float* __restrict__ A, const float* __restrict__ W,
                      const float* __restrict__ bias, float* __restrict__ C,
                      int M, int Nc, int K) {
    __shared__ float As[16][64];
    __shared__ float Bs[16][64];
    int tid = threadIdx.x;
    int rowBase = blockIdx.y * 64;
    int colBase = blockIdx.x * 64;
    int tx = tid & 15, ty = tid >> 4;
    int ldr = tid >> 2;
    int ldc = (tid & 3) * 4;
    float acc[4][4];
    #pragma unroll
    for (int i = 0; i < 4; i++)
        #pragma unroll
        for (int j = 0; j < 4; j++) acc[i][j] = 0.f;
    for (int k0 = 0; k0 < K; k0 += 16) {
        {
            int r = rowBase + ldr;
            float4 v = make_float4(0.f, 0.f, 0.f, 0.f);
            if (r < M) v = *reinterpret_cast<const float4*>(A + (size_t)r * K + k0 + ldc);
            As[ldc + 0][ldr] = v.x; As[ldc + 1][ldr] = v.y;
            As[ldc + 2][ldr] = v.z; As[ldc + 3][ldr] = v.w;
        }
        {
            int r = colBase + ldr;
            float4 v = make_float4(0.f, 0.f, 0.f, 0.f);
            if (r < Nc) v = *reinterpret_cast<const float4*>(W + (size_t)r * K + k0 + ldc);
            Bs[ldc + 0][ldr] = v.x; Bs[ldc + 1][ldr] = v.y;
            Bs[ldc + 2][ldr] = v.z; Bs[ldc + 3][ldr] = v.w;
        }
        __syncthreads();
        #pragma unroll
        for (int kk = 0; kk < 16; kk++) {
            float4 a4 = *reinterpret_cast<float4*>(&As[kk][ty * 4]);
            float4 b4 = *reinterpret_cast<float4*>(&Bs[kk][tx * 4]);
            float av[4] = {a4.x, a4.y, a4.z, a4.w};
            float bv[4] = {b4.x, b4.y, b4.z, b4.w};
            #pragma unroll
            for (int i = 0; i < 4; i++)
                #pragma unroll
                for (int j = 0; j < 4; j++) acc[i][j] += av[i] * bv[j];
        }
        __syncthreads();
    }
    #pragma unroll
    for (int i = 0; i < 4; i++) {
        int r = rowBase + ty * 4 + i;
        if (r >= M) continue;
        #pragma unroll
        for (int j = 0; j < 4; j++) {
            int c = colBase + tx * 4 + j;
            if (c >= Nc) continue;
            C[(size_t)r * Nc + c] = acc[i][j] + bias[c];
        }
    }
}

// ---------------- Attention: one block per (b,h), K/V staged in SMEM --
constexpr int KV_PAD  = 69;                       // odd stride -> conflict-free
constexpr int KV_ROWS = 256;                      // padded (NN=243)
constexpr int ATTN_SMEM_FLOATS = 2 * KV_ROWS * KV_PAD + 8 * 256 + 8 * 72;
constexpr int ATTN_SMEM = ATTN_SMEM_FLOATS * 4;   // 151,808 B

__global__ __launch_bounds__(256)
void attn2_kernel(const float* __restrict__ qkv,
                  const float* __restrict__ b_table,
                  float* __restrict__ o) {
    extern __shared__ float smat[];
    float* Ks = smat;
    float* Vs = smat + KV_ROWS * KV_PAD;
    float* Ps = smat + 2 * KV_ROWS * KV_PAD;   // 8 warps x 256
    float* Qs = Ps + 8 * 256;                  // 8 warps x 72

    int tid = threadIdx.x, w = tid >> 5, lane = tid & 31;
    int b = blockIdx.x >> 3, h = blockIdx.x & 7;
    const float scale = 0.12126781251816648f;  // 1/sqrt(68)

    const float* kb = qkv + (size_t)b * NN * TD + DD + h * HD;
    const float* vb = kb + DD;
    for (int idx = tid; idx < NN * HD; idx += 256) {
        int j = idx / HD, d = idx - j * HD;
        Ks[j * KV_PAD + d] = kb[(size_t)j * TD + d];
        Vs[j * KV_PAD + d] = vb[(size_t)j * TD + d];
    }
    __syncthreads();

    const float* brow = b_table + h * (2 * NN - 1);
    for (int i = w; i < NN; i += 8) {
        const float* qp = qkv + (size_t)(b * NN + i) * TD + h * HD;
        for (int d = lane; d < HD; d += 32) Qs[w * 72 + d] = qp[d];
        __syncwarp();

        float sc[8];
        #pragma unroll
        for (int jj = 0; jj < 8; jj++) sc[jj] = 0.f;
        int base0 = lane * KV_PAD;
        for (int d = 0; d < HD; d++) {
            float qd = Qs[w * 72 + d];
            #pragma unroll
            for (int jj = 0; jj < 8; jj++)
                sc[jj] += qd * Ks[base0 + jj * 32 * KV_PAD + d];
        }
        float m = -3.4e38f;
        #pragma unroll
        for (int jj = 0; jj < 8; jj++) {
            int j = jj * 32 + lane;
            if (j < NN) sc[jj] = sc[jj] * scale + brow[i - j + NN - 1];
            else        sc[jj] = -3.4e38f;
            m = fmaxf(m, sc[jj]);
        }
        #pragma unroll
        for (int off = 16; off > 0; off >>= 1)
            m = fmaxf(m, __shfl_xor_sync(0xffffffffu, m, off));
        float s = 0.f;
        #pragma unroll
        for (int jj = 0; jj < 8; jj++) {
            int j = jj * 32 + lane;
            if (j < NN) {
                float e = expf(sc[jj] - m);
                Ps[w * 256 + j] = e;
                s += e;
            }
        }
        #pragma unroll
        for (int off = 16; off > 0; off >>= 1)
            s += __shfl_xor_sync(0xffffffffu, s, off);
        float inv = 1.f / s;
        __syncwarp();

        float a0 = 0.f, a1 = 0.f, a2 = 0.f;
        for (int j = 0; j < NN; j++) {
            float pj = Ps[w * 256 + j];
            const float* vr = Vs + j * KV_PAD;
            a0 += pj * vr[lane];
            a1 += pj * vr[lane + 32];
            a2 += pj * vr[lane + 64];
        }
        float* orow = o + (size_t)(b * NN + i) * DD + h * HD;
        orow[lane]      = a0 * inv;
        orow[lane + 32] = a1 * inv;
        if (lane < HD - 64) orow[lane + 64] = a2 * inv;
        __syncwarp();
    }
}

// ---------------- Seed attention scores: a[b,h,n,f] ----------------
__global__ void seed_scores_kernel(const float* __restrict__ xu,
                                   const float* __restrict__ s0,
                                   float* __restrict__ a) {
    __shared__ float xs[UD];
    int t = blockIdx.x;              // token = b*NN + f
    int b = t / NN, f = t % NN;
    for (int i = threadIdx.x; i < UD; i += blockDim.x)
        xs[i] = xu[(size_t)t * UD + i];
    __syncthreads();
    int oi = threadIdx.x;
    if (oi < HH * NS) {
        int h = oi / NS, n = oi % NS;
        const float* sp = s0 + n * UD + h * UC;
        const float* xp = xs + h * UC;
        float accv = 0.f;
        #pragma unroll 8
        for (int c = 0; c < UC; c++) accv += xp[c] * sp[c];
        a[((size_t)(b * HH + h) * NS + n) * NN + f] = accv;
    }
}

// ---------------- softmax over f ----------
__global__ void softmax_f_kernel(float* __restrict__ a) {
    __shared__ float red[4];
    int row = blockIdx.x;
    float* p = a + (size_t)row * NN;
    float lmax = -3.4e38f;
    for (int f = threadIdx.x; f < NN; f += blockDim.x) lmax = fmaxf(lmax, p[f]);
    float m = block_max(lmax, red);
    float lsum = 0.f;
    for (int f = threadIdx.x; f < NN; f += blockDim.x) {
        float e = expf(p[f] - m);
        p[f] = e;
        lsum += e;
    }
    float s = block_sum(lsum, red);
    float inv = 1.f / s;
    for (int f = threadIdx.x; f < NN; f += blockDim.x) p[f] *= inv;
}

// ---------------- normalize over n ----------
__global__ void seed_norm_kernel(float* __restrict__ a) {
    int idx = blockIdx.x * blockDim.x + threadIdx.x;
    if (idx >= BSZ * HH * NN) return;
    int f  = idx % NN;
    int bh = idx / NN;
    float* base = a + (size_t)bh * NS * NN + f;
    float s = 0.f;
    #pragma unroll
    for (int n = 0; n < NS; n++) s += base[n * NN];
    float inv = 1.f / (1e-7f + s);
    #pragma unroll
    for (int n = 0; n < NS; n++) base[n * NN] *= inv;
}

// ---------------- mean_attn ----------------
__global__ void mean_kernel(const float* __restrict__ a, float* __restrict__ out_mean) {
    __shared__ float red[8];
    int n = blockIdx.x;
    float s = 0.f;
    int total = BSZ * HH * NN;
    for (int i = threadIdx.x; i < total; i += blockDim.x) {
        int f  = i % NN;
        int bh = i / NN;
        s += a[((size_t)bh * NS + n) * NN + f];
    }
    s = block_sum(s, red);
    if (threadIdx.x == 0) out_mean[n] = s * (1.0f / (BSZ * HH * NN));
}

// ---------------- o2[t, h*UC+c] = sum_n a * s1 ----------
__global__ void seed_out_kernel(const float* __restrict__ a,
                                const float* __restrict__ s1,
                                float* __restrict__ o2) {
    int idx = blockIdx.x * blockDim.x + threadIdx.x;
    if (idx >= BT * UD) return;
    int c    = idx % UC;
    int rest = idx / UC;
    int h    = rest % HH;
    int t    = rest / HH;
    int b = t / NN, f = t % NN;
    const float* ap = a + (size_t)(b * HH + h) * NS * NN + f;
    const float* sp = s1 + h * UC + c;
    float accv = 0.f;
    #pragma unroll
    for (int n = 0; n < NS; n++) accv += ap[n * NN] * sp[(size_t)n * UD];
    o2[idx] = accv;
}

// ---------------- driver ----------------
static inline dim3 tgrid(int M, int Nc) {
    return dim3((Nc + 127) / 128, (M + 127) / 128);
}

extern "C" void kernel_launch(void* const* d_in, const int* in_sizes, int n_in,
                              void* d_out, int out_size) {
    const float* x       = (const float*)d_in[0];
    const float* seed    = (const float*)d_in[1];
    const float* ln1_g   = (const float*)d_in[2];
    const float* ln1_b   = (const float*)d_in[3];
    const float* w_qkv   = (const float*)d_in[4];
    const float* w_proj  = (const float*)d_in[5];
    const float* b_proj  = (const float*)d_in[6];
    const float* b_table = (const float*)d_in[7];
    const float* ln2_g   = (const float*)d_in[8];
    const float* ln2_b   = (const float*)d_in[9];
    const float* mlp_w1  = (const float*)d_in[10];
    const float* mlp_b1  = (const float*)d_in[11];
    const float* mlp_w2  = (const float*)d_in[12];
    const float* mlp_b2  = (const float*)d_in[13];
    const float* eln1_g  = (const float*)d_in[14];
    const float* eln1_b  = (const float*)d_in[15];
    const float* w_trans = (const float*)d_in[16];
    const float* b_trans = (const float*)d_in[17];
    const float* w0      = (const float*)d_in[18];
    const float* b0      = (const float*)d_in[19];
    const float* w1      = (const float*)d_in[20];
    const float* b1      = (const float*)d_in[21];
    const float* w_proj2 = (const float*)d_in[22];
    const float* b_proj2 = (const float*)d_in[23];
    const float* eln2_g  = (const float*)d_in[24];
    const float* eln2_b  = (const float*)d_in[25];
    const float* emlp_w1 = (const float*)d_in[26];
    const float* emlp_b1 = (const float*)d_in[27];
    const float* emlp_w2 = (const float*)d_in[28];
    const float* emlp_b2 = (const float*)d_in[29];

    float* out = (float*)d_out;

    float *ph, *pqkv, *po, *px1, *px2, *px3, *pmlp, *pxu, *po2, *ps0, *ps1, *pa;
    cudaGetSymbolAddress((void**)&ph,   g_h);
    cudaGetSymbolAddress((void**)&pqkv, g_qkv);
    cudaGetSymbolAddress((void**)&po,   g_o);
    cudaGetSymbolAddress((void**)&px1,  g_x1);
    cudaGetSymbolAddress((void**)&px2,  g_x2);
    cudaGetSymbolAddress((void**)&px3,  g_x3);
    cudaGetSymbolAddress((void**)&pmlp, g_mlp);
    cudaGetSymbolAddress((void**)&pxu,  g_xu);
    cudaGetSymbolAddress((void**)&po2,  g_o2);
    cudaGetSymbolAddress((void**)&ps0,  g_s0);
    cudaGetSymbolAddress((void**)&ps1,  g_s1);
    cudaGetSymbolAddress((void**)&pa,   g_a);

    cudaFuncSetAttribute(mma_gemm<0>, cudaFuncAttributeMaxDynamicSharedMemorySize, GEMM_SMEM);
    cudaFuncSetAttribute(mma_gemm<1>, cudaFuncAttributeMaxDynamicSharedMemorySize, GEMM_SMEM);
    cudaFuncSetAttribute(mma_gemm<2>, cudaFuncAttributeMaxDynamicSharedMemorySize, GEMM_SMEM);
    cudaFuncSetAttribute(mma_gemm<3>, cudaFuncAttributeMaxDynamicSharedMemorySize, GEMM_SMEM);
    cudaFuncSetAttribute(attn2_kernel, cudaFuncAttributeMaxDynamicSharedMemorySize, ATTN_SMEM);

    // ---- block 1: self-attention + MLP ----
    ln_kernel<<<BT, 256>>>(x, ln1_g, ln1_b, ph);
    mma_gemm<0><<<tgrid(BT, TD), 256, GEMM_SMEM>>>(ph, w_qkv, nullptr, nullptr, pqkv, BT, TD, DD);
    attn2_kernel<<<BSZ * HH, 256, ATTN_SMEM>>>(pqkv, b_table, po);
    mma_gemm<3><<<tgrid(BT, DD), 256, GEMM_SMEM>>>(po, w_proj, b_proj, x, px1, BT, DD, DD);
    ln_kernel<<<BT, 256>>>(px1, ln2_g, ln2_b, ph);
    mma_gemm<2><<<tgrid(BT, MLP1), 256, GEMM_SMEM>>>(ph, mlp_w1, mlp_b1, nullptr, pmlp, BT, MLP1, DD);
    mma_gemm<3><<<tgrid(BT, DD), 256, GEMM_SMEM>>>(pmlp, mlp_w2, mlp_b2, px1, px2, BT, DD, MLP1);

    // ---- block 2: seed attention ----
    ln_kernel<<<BT, 256>>>(px2, eln1_g, eln1_b, ph);
    mma_gemm<1><<<tgrid(BT, UD), 256, GEMM_SMEM>>>(ph, w_trans, b_trans, nullptr, pxu, BT, UD, DD);
    gemm_scalar_bias<<<dim3((UD + 63) / 64, 1), 256>>>(seed, w0, b0, ps0, NS, UD, DD);
    gemm_scalar_bias<<<dim3((UD + 63) / 64, 1), 256>>>(seed, w1, b1, ps1, NS, UD, DD);
    seed_scores_kernel<<<BT, 160>>>(pxu, ps0, pa);
    softmax_f_kernel<<<BSZ * HH * NS, 128>>>(pa);
    seed_norm_kernel<<<(BSZ * HH * NN + 255) / 256, 256>>>(pa);
    mean_kernel<<<NS, 256>>>(pa, out + X_ELEMS);
    seed_out_kernel<<<(BT * UD + 255) / 256, 256>>>(pa, ps1, po2);
    mma_gemm<3><<<tgrid(BT, DD), 256, GEMM_SMEM>>>(po2, w_proj2, b_proj2, px2, px3, BT, DD, UD);

    // ---- block 3: final MLP (writes x into d_out) ----
    ln_kernel<<<BT, 256>>>(px3, eln2_g, eln2_b, ph);
    mma_gemm<2><<<tgrid(BT, MLP2), 256, GEMM_SMEM>>>(ph, emlp_w1, emlp_b1, nullptr, pmlp, BT, MLP2, DD);
    mma_gemm<3><<<tgrid(BT, DD), 256, GEMM_SMEM>>>(pmlp, emlp_w2, emlp_b2, px3, out, BT, DD, MLP2);
}